// round 4
// baseline (speedup 1.0000x reference)
#include <cuda_runtime.h>
#include <cstdint>

// DynamicRoIAlign: feat (8,256,160,160) f32 NCHW, rois (1024,5) f32
// [b, x1, y1, x2, y2] normalized; SCALE_H = SCALE_W = 160; ALIGNED = False.
// Output (K, 256, 14, 14) f32.
//
// ALIGNED=False math from reference:
//   fx = x1*160 + gx*(x2-x1)*160 ; ngx = fx/W*2-1 ; ix = ((ngx+1)*W-1)*0.5
//   => ix = fx - 0.5   (exact algebraic collapse)

#define OH 14
#define OW 14
#define NPOS (OH * OW)        // 196
#define CCH 256
#define FH 160
#define FW 160
#define FHW (FH * FW)         // 25600
#define SCALE 160.0f

__global__ __launch_bounds__(256, 8)
void roi_align_kernel(const float* __restrict__ feat,
                      const float* __restrict__ rois,
                      float* __restrict__ out)
{
    const int k = blockIdx.x;
    const int t = threadIdx.x;

    __shared__ int4   s_off[NPOS];   // 4 clamped linear offsets (y*W + x) per pos
    __shared__ float4 s_w[NPOS];     // 4 combined weights per pos
    __shared__ float  s_roi[5];
    __shared__ int    s_base;        // b * C * H * W

    if (t < 5) s_roi[t] = rois[k * 5 + t];
    __syncthreads();

    if (t < NPOS) {
        const int oy = t / OW;
        const int ox = t - oy * OW;

        const float x1 = s_roi[1] * SCALE;
        const float y1 = s_roi[2] * SCALE;
        const float x2 = s_roi[3] * SCALE;
        const float y2 = s_roi[4] * SCALE;

        const float gx = (float)ox * (1.0f / (OW - 1));
        const float gy = (float)oy * (1.0f / (OH - 1));
        const float fx = x1 + gx * (x2 - x1);
        const float fy = y1 + gy * (y2 - y1);

        // ALIGNED=False: ix = fx - 0.5, iy = fy - 0.5
        const float ix = fx - 0.5f;
        const float iy = fy - 0.5f;

        const float fx0 = floorf(ix);
        const float fy0 = floorf(iy);
        const int   x0  = (int)fx0;
        const int   y0  = (int)fy0;
        const int   x1i = x0 + 1;
        const int   y1i = y0 + 1;

        const float wx1 = ix - fx0;
        const float wx0 = 1.0f - wx1;
        const float wy1 = iy - fy0;
        const float wy0 = 1.0f - wy1;

        const float vx0 = (x0  >= 0 && x0  < FW) ? 1.0f : 0.0f;
        const float vx1 = (x1i >= 0 && x1i < FW) ? 1.0f : 0.0f;
        const float vy0 = (y0  >= 0 && y0  < FH) ? 1.0f : 0.0f;
        const float vy1 = (y1i >= 0 && y1i < FH) ? 1.0f : 0.0f;

        const int x0c = min(max(x0,  0), FW - 1);
        const int x1c = min(max(x1i, 0), FW - 1);
        const int y0c = min(max(y0,  0), FH - 1);
        const int y1c = min(max(y1i, 0), FH - 1);

        int4 o;
        o.x = y0c * FW + x0c;
        o.y = y0c * FW + x1c;
        o.z = y1c * FW + x0c;
        o.w = y1c * FW + x1c;
        s_off[t] = o;

        float4 w;
        w.x = wy0 * wx0 * vy0 * vx0;
        w.y = wy0 * wx1 * vy0 * vx1;
        w.z = wy1 * wx0 * vy1 * vx0;
        w.w = wy1 * wx1 * vy1 * vx1;
        s_w[t] = w;
    }
    if (t == 0) s_base = (int)s_roi[0] * (CCH * FHW);
    __syncthreads();

    const float* fb   = feat + s_base;
    float*       outk = out + (size_t)k * (CCH * NPOS);

    // 50176 outputs per roi; thread-linear over out index (ox fastest) ->
    // fully coalesced writes. pos = idx % 196, c = idx / 196.
    // unroll 4: 16 independent LDGs in flight per thread for latency hiding.
    #pragma unroll 4
    for (int idx = t; idx < CCH * NPOS; idx += 256) {
        const int c   = idx / NPOS;
        const int pos = idx - c * NPOS;

        const int4   o = s_off[pos];
        const float4 w = s_w[pos];
        const float* f = fb + c * FHW;

        float v = __ldg(f + o.x) * w.x
                + __ldg(f + o.y) * w.y
                + __ldg(f + o.z) * w.z
                + __ldg(f + o.w) * w.w;
        outk[idx] = v;
    }
}

extern "C" void kernel_launch(void* const* d_in, const int* in_sizes, int n_in,
                              void* d_out, int out_size)
{
    const float* feat = (const float*)d_in[0];
    const float* rois = (const float*)d_in[1];
    float*       out  = (float*)d_out;

    const int K = in_sizes[1] / 5;   // 1024

    roi_align_kernel<<<K, 256>>>(feat, rois, out);
}